// round 2
// baseline (speedup 1.0000x reference)
#include <cuda_runtime.h>

#define TT 512
#define CC 256
#define LL 128
#define SS 257          // 2L+1
#define NWARP 9
#define NTHREADS 288    // 9 warps

__global__ __launch_bounds__(NTHREADS, 2)
void ctc_fwd_kernel(const int* __restrict__ y_true,
                    const float* __restrict__ y_pred,
                    float* __restrict__ out)
{
    const int b   = blockIdx.x;
    const int tid = threadIdx.x;
    const float EPS = 1e-7f;

    __shared__ float P[2][CC];          // double-buffered prob row (y_pred + eps)
    __shared__ float A[2][SS + 2];      // alpha, index shifted by 2; A[q][0..1] = 0 pads
    __shared__ float wmax[2][NWARP];    // per-warp maxima, double buffered
    __shared__ int   ecls[SS];          // extended symbol class per lane

    // ---- one-time setup: extended label + skip flag ----
    int   myc  = CC - 1;   // blank
    float mysk = 0.f;
    if (tid < SS) {
        if (tid & 1) {
            const int j = tid >> 1;
            myc  = y_true[b * LL + j];
            mysk = (j >= 1 && myc != y_true[b * LL + j - 1]) ? 1.f : 0.f;
        }
        ecls[tid] = myc;
    }
    if (tid < 2) { A[0][tid] = 0.f; A[1][tid] = 0.f; }

    const float* base = y_pred + (size_t)b * TT * CC;

    // load rows 0 and 1 (64 float4 each)
    if (tid < 128) {
        const int r = tid >> 6;          // 0 or 1
        const int i = tid & 63;
        const float4 v = reinterpret_cast<const float4*>(base + r * CC)[i];
        P[r][i * 4 + 0] = v.x + EPS;
        P[r][i * 4 + 1] = v.y + EPS;
        P[r][i * 4 + 2] = v.z + EPS;
        P[r][i * 4 + 3] = v.w + EPS;
    }
    __syncthreads();

    // ---- alpha0: only s=0 (blank) and s=1 (first label) live ----
    float v0 = 0.f;
    if (tid < SS) {
        v0 = (tid < 2) ? P[0][myc] : 0.f;
        A[0][2 + tid] = v0;
    }
    float wm = v0;
    #pragma unroll
    for (int o = 16; o; o >>= 1) wm = fmaxf(wm, __shfl_xor_sync(0xffffffffu, wm, o));
    if ((tid & 31) == 0) wmax[0][tid >> 5] = wm;
    __syncthreads();

    int esum = 0;

    // ---- main recursion: t = 1 .. T-1, ONE barrier per step ----
    for (int t = 1; t < TT; ++t) {
        const int qa = (t - 1) & 1;   // alpha source / wmax source
        const int qn = t & 1;         // alpha dest / current P row

        // block max of previous step -> exact power-of-two scale
        float m = fmaxf(fmaxf(fmaxf(wmax[qa][0], wmax[qa][1]),
                              fmaxf(wmax[qa][2], wmax[qa][3])),
                        fmaxf(fmaxf(wmax[qa][4], wmax[qa][5]),
                              fmaxf(wmax[qa][6], wmax[qa][7])));
        m = fmaxf(m, wmax[qa][8]);
        const int e = (int)(__float_as_uint(m) >> 23) - 127;
        esum += e;
        const float scl = __uint_as_float((unsigned)(127 - e) << 23);

        // prefetch row t+1 into registers (hides DRAM latency behind compute)
        float4 pre;
        const bool havepre = (tid < 64) && (t + 1 < TT);
        if (havepre)
            pre = reinterpret_cast<const float4*>(base + (size_t)(t + 1) * CC)[tid];

        // alpha update (linear domain, normalized)
        float v = 0.f;
        if (tid < SS) {
            const float a0 = A[qa][2 + tid];
            const float a1 = A[qa][1 + tid];
            const float a2 = A[qa][0 + tid];
            const float p  = P[qn][myc];
            v = (a0 + a1 + mysk * a2) * (p * scl);
        }

        // warp-level max of new alphas
        float wmv = v;
        #pragma unroll
        for (int o = 16; o; o >>= 1) wmv = fmaxf(wmv, __shfl_xor_sync(0xffffffffu, wmv, o));

        if (tid < SS) A[qn][2 + tid] = v;
        if ((tid & 31) == 0) wmax[qn][tid >> 5] = wmv;

        if (havepre) {
            float* Pd = P[(t + 1) & 1];
            Pd[tid * 4 + 0] = pre.x + EPS;
            Pd[tid * 4 + 1] = pre.y + EPS;
            Pd[tid * 4 + 2] = pre.z + EPS;
            Pd[tid * 4 + 3] = pre.w + EPS;
        }
        __syncthreads();
    }

    if (tid == 0) {
        const int qf = (TT - 1) & 1;
        const float s2 = A[qf][2 + SS - 1] + A[qf][2 + SS - 2];
        out[b] = -(logf(s2) + 0.69314718055994530942f * (float)esum);
    }
}

extern "C" void kernel_launch(void* const* d_in, const int* in_sizes, int n_in,
                              void* d_out, int out_size)
{
    // metadata order: y_true (int32, 256*128), y_pred (fp32, 256*512*256).
    // Defensive: pick by size so a swapped order still works.
    const int* yt;
    const float* yp;
    if (in_sizes[0] < in_sizes[1]) {
        yt = (const int*)d_in[0];
        yp = (const float*)d_in[1];
    } else {
        yt = (const int*)d_in[1];
        yp = (const float*)d_in[0];
    }
    ctc_fwd_kernel<<<256, NTHREADS>>>(yt, yp, (float*)d_out);
}

// round 3
// speedup vs baseline: 2.3382x; 2.3382x over previous
#include <cuda_runtime.h>

#define TT 512
#define CC 256
#define LL 128
#define SS 257          // 2L+1
#define NWARP 9
#define NTHREADS 288
#define PAD 8
#define EPSF 1e-7f

struct Smem {
    float A[2][PAD + SS];     // alpha, front-padded with zeros
    float P[2][4][CC];        // double-buffered groups of 4 prob rows (+eps)
    float wmax[2][NWARP];     // per-warp maxima, double buffered
    int   ecls[SS];           // extended symbol class
    float eskip[SS];          // skip-transition flag (0/1)
};

__device__ __forceinline__ float warp_max(float v) {
    #pragma unroll
    for (int o = 16; o; o >>= 1) v = fmaxf(v, __shfl_xor_sync(0xffffffffu, v, o));
    return v;
}

// Advance K time steps with ONE barrier. Thread s recomputes the dependency
// cone from alpha[s-2K..s] down to the single cell alpha_new[s].
template<int K>
__device__ __forceinline__ void step_block(
    Smem& sm, int srcA, int dstA, int pbuf, int roff,
    const float* gpre, int pfb,
    const int cls[7], const float skp[7],
    int s, int tid, int& esum)
{
    // block max from previous iteration -> exact power-of-two rescale
    float m = sm.wmax[srcA][0];
    #pragma unroll
    for (int w = 1; w < NWARP; ++w) m = fmaxf(m, sm.wmax[srcA][w]);
    const int e = (int)(__float_as_uint(m) >> 23) - 127;
    esum += e;
    const float scl = __uint_as_float((unsigned)(127 - e) << 23);

    // prefetch next 4 prob rows (1 float4 per thread, threads 0..255)
    float4 pre;
    const bool havepre = (gpre != nullptr) && (tid < 256);
    if (havepre) pre = reinterpret_cast<const float4*>(gpre)[tid];

    const bool act = (tid < SS);

    // load + rescale the 2K+1 alpha inputs (front pad of A supplies zeros)
    float v[2 * K + 1];
    #pragma unroll
    for (int d = 0; d <= 2 * K; ++d)
        v[d] = act ? sm.A[srcA][s + d + (PAD - 2 * K)] * scl : 0.f;

    // K recursion levels over the shrinking cone
    #pragma unroll
    for (int r = 0; r < K; ++r) {
        const float* Pr = sm.P[pbuf][roff + r];
        const int w = 2 * (K - 1 - r) + 1;
        #pragma unroll
        for (int d = 0; d < w; ++d) {
            const int off = (w - 1) - d;     // = s - pos
            float nv = 0.f;
            if (act && s >= off) {
                const float t0 = v[d + 2] + v[d + 1];
                const float t1 = fmaf(skp[off], v[d], t0);
                nv = t1 * Pr[cls[off]];
            }
            v[d] = nv;
        }
    }

    const float fin = v[0];
    const float wm = warp_max(fin);
    if (act) sm.A[dstA][PAD + s] = fin;
    if ((tid & 31) == 0) sm.wmax[dstA][tid >> 5] = wm;

    if (havepre) {
        float* dst = &sm.P[pfb][tid >> 6][(tid & 63) * 4];
        dst[0] = pre.x + EPSF;
        dst[1] = pre.y + EPSF;
        dst[2] = pre.z + EPSF;
        dst[3] = pre.w + EPSF;
    }
    __syncthreads();
}

__global__ __launch_bounds__(NTHREADS, 2)
void ctc_fwd4(const int* __restrict__ y_true,
              const float* __restrict__ y_pred,
              float* __restrict__ out)
{
    __shared__ Smem sm;
    const int b = blockIdx.x;
    const int tid = threadIdx.x;
    const int s = tid;
    const float* base = y_pred + (size_t)b * TT * CC;

    // ---- setup: extended label, skip flags, pads, first 4 prob rows ----
    if (tid < SS) {
        int c = CC - 1; float sk = 0.f;
        if (tid & 1) {
            const int j = tid >> 1;
            c = y_true[b * LL + j];
            sk = (j >= 1 && c != y_true[b * LL + j - 1]) ? 1.f : 0.f;
        }
        sm.ecls[tid] = c;
        sm.eskip[tid] = sk;
    }
    if (tid < PAD) { sm.A[0][tid] = 0.f; sm.A[1][tid] = 0.f; }
    if (tid < 256) {
        const float4 v = reinterpret_cast<const float4*>(base)[tid];
        float* dst = &sm.P[0][tid >> 6][(tid & 63) * 4];
        dst[0] = v.x + EPSF; dst[1] = v.y + EPSF;
        dst[2] = v.z + EPSF; dst[3] = v.w + EPSF;
    }
    __syncthreads();

    // per-thread class/skip registers for offsets 0..6 (pos = s - off)
    int cls[7]; float skp[7];
    #pragma unroll
    for (int o = 0; o < 7; ++o) {
        const int pos = s - o;
        const bool ok = (s < SS) && (pos >= 0);
        cls[o] = ok ? sm.ecls[pos] : 0;
        skp[o] = ok ? sm.eskip[pos] : 0.f;
    }

    // ---- alpha0: lanes 0 (blank) and 1 (first label) ----
    float v0 = 0.f;
    if (tid < SS) {
        v0 = (tid < 2) ? sm.P[0][0][cls[0]] : 0.f;
        sm.A[0][PAD + tid] = v0;
    }
    const float wm0 = warp_max(v0);
    if ((tid & 31) == 0) sm.wmax[0][tid >> 5] = wm0;
    __syncthreads();

    int esum = 0;

    // steps t=1..3 from P[0] slots 1..3; prefetch rows 4..7 -> P[1]
    step_block<3>(sm, 0, 1, 0, 1, base + 4 * CC, 1, cls, skp, s, tid, esum);

    // 127 blocks of 4 steps: rows 4+4j .. 7+4j
    for (int j = 0; j < 127; ++j) {
        const int pb   = (j + 1) & 1;
        const int srcA = (j + 1) & 1;
        const int dstA = j & 1;
        const float* gpre = (j < 126) ? base + (size_t)(8 + 4 * j) * CC : nullptr;
        step_block<4>(sm, srcA, dstA, pb, 0, gpre, j & 1, cls, skp, s, tid, esum);
    }

    if (tid == 0) {
        // last dstA = 126 & 1 = 0
        const float s2 = sm.A[0][PAD + SS - 1] + sm.A[0][PAD + SS - 2];
        out[b] = -(logf(s2) + 0.69314718055994530942f * (float)esum);
    }
}

extern "C" void kernel_launch(void* const* d_in, const int* in_sizes, int n_in,
                              void* d_out, int out_size)
{
    const int* yt;
    const float* yp;
    if (in_sizes[0] < in_sizes[1]) {
        yt = (const int*)d_in[0];
        yp = (const float*)d_in[1];
    } else {
        yt = (const int*)d_in[1];
        yp = (const float*)d_in[0];
    }
    ctc_fwd4<<<256, NTHREADS>>>(yt, yp, (float*)d_out);
}